// round 5
// baseline (speedup 1.0000x reference)
#include <cuda_runtime.h>

#define BATCH 4
#define CCH   32
#define HH    512
#define WW    960
#define HT    128
#define WT    240
#define HW    (HH*WW)      // 491520
#define HTWT  (HT*WT)      // 30720

__global__ __launch_bounds__(256)
void tile_warp_kernel(const float* __restrict__ tp,
                      const float* __restrict__ fl,
                      const float* __restrict__ fr,
                      float* __restrict__ out)
{
    int idx = blockIdx.x * blockDim.x + threadIdx.x;   // over B*H*W
    int x = idx % WW;
    int y = (idx / WW) % HH;
    int b = idx / (HH * WW);

    int ht = y >> 2, wt = x >> 2;
    int i  = y & 3,  j  = x & 3;

    int tbase = b * 3 * HTWT + ht * WT + wt;
    float d   = tp[tbase];
    float ddx = tp[tbase + HTWT];
    float ddy = tp[tbase + 2 * HTWT];

    // dd=0 hypothesis source position
    float disp0 = d + ((float)i - 1.5f) * ddy + ((float)j - 1.5f) * ddx;
    float s   = (float)x - disp0;
    float x0f = floorf(s);
    float w   = s - x0f;
    int   x0  = (int)x0f;

    // validity masks: x_src in [0, W-1] for x_src = s+1 (dd=-1), s (dd=0), s-1 (dd=+1)
    float mm1 = (s >= -1.f && s <= (float)(WW - 2)) ? 1.f : 0.f;
    float m0  = (s >=  0.f && s <= (float)(WW - 1)) ? 1.f : 0.f;
    float mp1 = (s >=  1.f && s <= (float)(WW))     ? 1.f : 0.f;

    // 4 clamped taps cover all 3 hypotheses
    int i0 = min(max(x0 - 1, 0), WW - 1);
    int i1 = min(max(x0    , 0), WW - 1);
    int i2 = min(max(x0 + 1, 0), WW - 1);
    int i3 = min(max(x0 + 2, 0), WW - 1);

    const float* flp = fl + (size_t)b * CCH * HW + (size_t)y * WW + x;
    const float* frp = fr + (size_t)b * CCH * HW + (size_t)y * WW;

    float cm1 = 0.f, c0 = 0.f, cp1 = 0.f;

#pragma unroll 4
    for (int c = 0; c < CCH; c++) {
        float a  = __ldg(flp + (size_t)c * HW);
        const float* row = frp + (size_t)c * HW;
        float g0 = __ldg(row + i0);
        float g1 = __ldg(row + i1);
        float g2 = __ldg(row + i2);
        float g3 = __ldg(row + i3);
        // dd=-1: taps (g2,g3); dd=0: (g1,g2); dd=+1: (g0,g1); shared frac w
        cm1 += fabsf(a - mm1 * (g2 + w * (g3 - g2)));
        c0  += fabsf(a - m0  * (g1 + w * (g2 - g1)));
        cp1 += fabsf(a - mp1 * (g0 + w * (g1 - g0)));
    }

    int obase = b * 48 * HTWT + (i * 4 + j) * HTWT + ht * WT + wt;
    out[obase]             = cm1;   // hypothesis dd=-1 -> channels 0..15
    out[obase + 16 * HTWT] = c0;    // dd= 0 -> channels 16..31
    out[obase + 32 * HTWT] = cp1;   // dd=+1 -> channels 32..47
}

extern "C" void kernel_launch(void* const* d_in, const int* in_sizes, int n_in,
                              void* d_out, int out_size)
{
    // Defensive input mapping: tile_plane is the small tensor (368640 elems);
    // the two large ones keep their relative order (fea_l, then fea_r).
    const float* tp = nullptr;
    const float* big[2] = {nullptr, nullptr};
    int nbig = 0;
    for (int k = 0; k < n_in; k++) {
        if (in_sizes[k] == BATCH * 3 * HTWT) {
            tp = (const float*)d_in[k];
        } else if (nbig < 2) {
            big[nbig++] = (const float*)d_in[k];
        }
    }
    const float* fl = big[0];
    const float* fr = big[1];
    float* out = (float*)d_out;

    int total = BATCH * HH * WW;          // 1,966,080
    int threads = 256;
    int blocks = (total + threads - 1) / threads;  // 7680
    tile_warp_kernel<<<blocks, threads>>>(tp, fl, fr, out);
}

// round 6
// speedup vs baseline: 1.0018x; 1.0018x over previous
#include <cuda_runtime.h>

#define BATCH 4
#define CCH   32
#define HH    512
#define WW    960
#define HT    128
#define WT    240
#define HW    (HH*WW)      // 491520
#define HTWT  (HT*WT)      // 30720

__global__ __launch_bounds__(256)
void tile_warp_kernel(const float* __restrict__ tp,
                      const float* __restrict__ fl,
                      const float* __restrict__ fr,
                      float* __restrict__ out)
{
    int idx = blockIdx.x * blockDim.x + threadIdx.x;   // over B*H*W
    int x = idx % WW;
    int y = (idx / WW) % HH;
    int b = idx / (HH * WW);

    int ht = y >> 2, wt = x >> 2;
    int i  = y & 3,  j  = x & 3;

    int tbase = b * 3 * HTWT + ht * WT + wt;
    float d   = tp[tbase];
    float ddx = tp[tbase + HTWT];
    float ddy = tp[tbase + 2 * HTWT];

    // dd=0 hypothesis source position
    float disp0 = d + ((float)i - 1.5f) * ddy + ((float)j - 1.5f) * ddx;
    float s   = (float)x - disp0;
    float x0f = floorf(s);
    float w   = s - x0f;
    int   x0  = (int)x0f;

    // validity masks: x_src in [0, W-1] for x_src = s+1 (dd=-1), s (dd=0), s-1 (dd=+1)
    float mm1 = (s >= -1.f && s <= (float)(WW - 2)) ? 1.f : 0.f;
    float m0  = (s >=  0.f && s <= (float)(WW - 1)) ? 1.f : 0.f;
    float mp1 = (s >=  1.f && s <= (float)(WW))     ? 1.f : 0.f;

    // 4 clamped taps cover all 3 hypotheses
    int i0 = min(max(x0 - 1, 0), WW - 1);
    int i1 = min(max(x0    , 0), WW - 1);
    int i2 = min(max(x0 + 1, 0), WW - 1);
    int i3 = min(max(x0 + 2, 0), WW - 1);

    const float* flp = fl + (size_t)b * CCH * HW + (size_t)y * WW + x;
    const float* frp = fr + (size_t)b * CCH * HW + (size_t)y * WW;

    float cm1 = 0.f, c0 = 0.f, cp1 = 0.f;

#pragma unroll 4
    for (int c = 0; c < CCH; c++) {
        float a  = __ldg(flp + (size_t)c * HW);
        const float* row = frp + (size_t)c * HW;
        float g0 = __ldg(row + i0);
        float g1 = __ldg(row + i1);
        float g2 = __ldg(row + i2);
        float g3 = __ldg(row + i3);
        // dd=-1: taps (g2,g3); dd=0: (g1,g2); dd=+1: (g0,g1); shared frac w
        cm1 += fabsf(a - mm1 * (g2 + w * (g3 - g2)));
        c0  += fabsf(a - m0  * (g1 + w * (g2 - g1)));
        cp1 += fabsf(a - mp1 * (g0 + w * (g1 - g0)));
    }

    int obase = b * 48 * HTWT + (i * 4 + j) * HTWT + ht * WT + wt;
    out[obase]             = cm1;   // hypothesis dd=-1 -> channels 0..15
    out[obase + 16 * HTWT] = c0;    // dd= 0 -> channels 16..31
    out[obase + 32 * HTWT] = cp1;   // dd=+1 -> channels 32..47
}

extern "C" void kernel_launch(void* const* d_in, const int* in_sizes, int n_in,
                              void* d_out, int out_size)
{
    // Defensive input mapping: tile_plane is the small tensor (368640 elems);
    // the two large ones keep their relative order (fea_l, then fea_r).
    const float* tp = nullptr;
    const float* big[2] = {nullptr, nullptr};
    int nbig = 0;
    for (int k = 0; k < n_in; k++) {
        if (in_sizes[k] == BATCH * 3 * HTWT) {
            tp = (const float*)d_in[k];
        } else if (nbig < 2) {
            big[nbig++] = (const float*)d_in[k];
        }
    }
    const float* fl = big[0];
    const float* fr = big[1];
    float* out = (float*)d_out;

    int total = BATCH * HH * WW;          // 1,966,080
    int threads = 256;
    int blocks = (total + threads - 1) / threads;  // 7680
    tile_warp_kernel<<<blocks, threads>>>(tp, fl, fr, out);
}